// round 2
// baseline (speedup 1.0000x reference)
#include <cuda_runtime.h>

// RestrictedNN on GB300: B=4096, N_INP=4096, L0=512 (G=8,H=16), L1=64, L2=8.
// f32x2 packed math: each 64-bit value holds {rowA, rowB} of a batch-row pair.
// Pair p in row-tile bx covers rows (bx*64+p, bx*64+p+32), p in [0,32).

#define NINP 4096
#define B_TOT 4096

typedef unsigned long long u64;

__device__ u64 g_h1[(size_t)2048 * 1024];   // [pair][g*16+h] packed pairs, 16 MB

__device__ __forceinline__ u64 pack2(float lo, float hi) {
    u64 r; asm("mov.b64 %0, {%1, %2};" : "=l"(r) : "f"(lo), "f"(hi)); return r;
}
__device__ __forceinline__ void unpack2(u64 v, float& lo, float& hi) {
    asm("mov.b64 {%0, %1}, %2;" : "=f"(lo), "=f"(hi) : "l"(v));
}
__device__ __forceinline__ u64 ffma2(u64 a, u64 b, u64 c) {
    u64 d; asm("fma.rn.f32x2 %0, %1, %2, %3;" : "=l"(d) : "l"(a), "l"(b), "l"(c));
    return d;
}
__device__ __forceinline__ u64 sig2(u64 z) {
    float a, b; unpack2(z, a, b);
    float ea, eb, ra, rb;
    asm("ex2.approx.f32 %0, %1;" : "=f"(ea) : "f"(a * -1.44269504f));
    asm("ex2.approx.f32 %0, %1;" : "=f"(eb) : "f"(b * -1.44269504f));
    asm("rcp.approx.f32 %0, %1;" : "=f"(ra) : "f"(1.0f + ea));
    asm("rcp.approx.f32 %0, %1;" : "=f"(rb) : "f"(1.0f + eb));
    return pack2(ra, rb);
}

// ---------------------------------------------------------------------------
// K1: grid (64 row-tiles, 64 groups), 256 threads = 16 h x 16 slots.
// slot handles pairs (slot, slot+16). Dynamic smem ~78 KB.
// ---------------------------------------------------------------------------
__global__ __launch_bounds__(256) void k1(
    const float* __restrict__ x, const float* __restrict__ Wg,
    const float* __restrict__ bgp, const float* __restrict__ W0,
    const float* __restrict__ W1)
{
    extern __shared__ __align__(16) unsigned char smraw[];
    u64* xs     = (u64*)smraw;                 // [32][66]  pairs x genes
    u64* w0d    = xs + 32 * 66;                // [(l*16+h)*10 + j]   dup'd
    u64* bias0d = w0d + 8 * 16 * 10;           // [l*16+h]            dup'd
    u64* h0s    = bias0d + 128;                // [32][130]
    u64* w1d    = h0s + 32 * 130;              // [h*130 + k]         dup'd

    const int g    = blockIdx.y;
    const int row0 = blockIdx.x * 64;
    const int tid  = threadIdx.x;
    const int h    = tid & 15;
    const int slot = tid >> 4;

    // --- stage x tile (64 rows x 64 genes) as pair-packed u64 ---
    #pragma unroll
    for (int it = 0; it < 4; ++it) {
        int idx = tid + 256 * it;              // [0,1024)
        int row = idx >> 4, c4 = idx & 15;
        float4 v = ((const float4*)(x + (size_t)(row0 + row) * NINP + g * 64))[c4];
        int p = row & 31, half = row >> 5;
        float* dst = (float*)xs + (p * 66 + c4 * 4) * 2 + half;
        dst[0] = v.x; dst[2] = v.y; dst[4] = v.z; dst[6] = v.w;
    }
    // --- stage fused gene*W0 weights, duplicated: w0d[(l*16+h)*10 + j] ---
    {
        int i = tid * 4;                       // 1024 elems exactly
        float4 v = ((const float4*)(W0 + (size_t)g * 1024))[tid];
        float wg = Wg[g * 64 + (i >> 4)];
        int l = i >> 7, j = (i >> 4) & 7, hh = i & 15;
        w0d[(l * 16 + hh + 0) * 10 + j] = pack2(v.x * wg, v.x * wg);
        w0d[(l * 16 + hh + 1) * 10 + j] = pack2(v.y * wg, v.y * wg);
        w0d[(l * 16 + hh + 2) * 10 + j] = pack2(v.z * wg, v.z * wg);
        w0d[(l * 16 + hh + 3) * 10 + j] = pack2(v.w * wg, v.w * wg);
    }
    // --- stage w1d transposed+dup: W1[g] is [k=128][h=16] -> w1d[h*130+k] ---
    #pragma unroll
    for (int it = 0; it < 2; ++it) {
        int i4 = tid + 256 * it;               // 512 float4
        int i = i4 * 4;
        float4 v = ((const float4*)(W1 + (size_t)g * 2048))[i4];
        int k = i >> 4, hh = i & 15;
        w1d[(hh + 0) * 130 + k] = pack2(v.x, v.x);
        w1d[(hh + 1) * 130 + k] = pack2(v.y, v.y);
        w1d[(hh + 2) * 130 + k] = pack2(v.z, v.z);
        w1d[(hh + 3) * 130 + k] = pack2(v.w, v.w);
    }
    // --- bias0d[l*16+h] = sum_j bg[g,l,j] * W0[g,l,j,h], duplicated ---
    if (tid < 128) {
        int l = tid >> 4, hh = tid & 15;
        const float* bgl = bgp + g * 64 + l * 8;
        const float* w0l = W0 + (size_t)g * 1024 + l * 128 + hh;
        float a = 0.f;
        #pragma unroll
        for (int j = 0; j < 8; ++j) a += bgl[j] * w0l[j * 16];
        bias0d[tid] = pack2(a, a);
    }
    __syncthreads();

    // --- h0: per leaf l, weights in regs, 2 pairs per thread ---
    #pragma unroll
    for (int l = 0; l < 8; ++l) {
        const ulonglong2* wv = (const ulonglong2*)&w0d[(l * 16 + h) * 10];
        ulonglong2 w0_ = wv[0], w1_ = wv[1], w2_ = wv[2], w3_ = wv[3];
        const u64 bb = bias0d[l * 16 + h];
        #pragma unroll
        for (int pp = 0; pp < 2; ++pp) {
            const int p = slot + pp * 16;
            const ulonglong2* xv = (const ulonglong2*)&xs[p * 66 + l * 8];
            ulonglong2 x0 = xv[0], x1 = xv[1], x2 = xv[2], x3 = xv[3];
            u64 acc = bb;
            acc = ffma2(x0.x, w0_.x, acc); acc = ffma2(x0.y, w0_.y, acc);
            acc = ffma2(x1.x, w1_.x, acc); acc = ffma2(x1.y, w1_.y, acc);
            acc = ffma2(x2.x, w2_.x, acc); acc = ffma2(x2.y, w2_.y, acc);
            acc = ffma2(x3.x, w3_.x, acc); acc = ffma2(x3.y, w3_.y, acc);
            h0s[p * 130 + l * 16 + h] = sig2(acc);
        }
    }
    __syncthreads();

    // --- h1: k-chunks of 8, weights in regs, 2 pair-accumulators ---
    {
        u64 acc0 = 0ull, acc1 = 0ull;
        const u64* wrow = &w1d[h * 130];
        const u64* a0r  = &h0s[slot * 130];
        const u64* a1r  = &h0s[(slot + 16) * 130];
        #pragma unroll
        for (int kc = 0; kc < 128; kc += 8) {
            const ulonglong2* wv = (const ulonglong2*)(wrow + kc);
            ulonglong2 w0_ = wv[0], w1_ = wv[1], w2_ = wv[2], w3_ = wv[3];
            const ulonglong2* av0 = (const ulonglong2*)(a0r + kc);
            ulonglong2 a0 = av0[0], a1 = av0[1], a2 = av0[2], a3 = av0[3];
            acc0 = ffma2(a0.x, w0_.x, acc0); acc0 = ffma2(a0.y, w0_.y, acc0);
            acc0 = ffma2(a1.x, w1_.x, acc0); acc0 = ffma2(a1.y, w1_.y, acc0);
            acc0 = ffma2(a2.x, w2_.x, acc0); acc0 = ffma2(a2.y, w2_.y, acc0);
            acc0 = ffma2(a3.x, w3_.x, acc0); acc0 = ffma2(a3.y, w3_.y, acc0);
            const ulonglong2* av1 = (const ulonglong2*)(a1r + kc);
            ulonglong2 b0 = av1[0], b1 = av1[1], b2 = av1[2], b3 = av1[3];
            acc1 = ffma2(b0.x, w0_.x, acc1); acc1 = ffma2(b0.y, w0_.y, acc1);
            acc1 = ffma2(b1.x, w1_.x, acc1); acc1 = ffma2(b1.y, w1_.y, acc1);
            acc1 = ffma2(b2.x, w2_.x, acc1); acc1 = ffma2(b2.y, w2_.y, acc1);
            acc1 = ffma2(b3.x, w3_.x, acc1); acc1 = ffma2(b3.y, w3_.y, acc1);
        }
        size_t pgA = (size_t)blockIdx.x * 32 + slot;
        g_h1[pgA * 1024 + g * 16 + h]        = sig2(acc0);
        g_h1[(pgA + 16) * 1024 + g * 16 + h] = sig2(acc1);
    }
}

// ---------------------------------------------------------------------------
// K2: grid 256, 128 threads = 16 h x 8 pair-slots. Dynamic smem ~84.5 KB.
// h2 (8 modules 128->16), root (128->16), final dot(16). Pair-packed acts.
// ---------------------------------------------------------------------------
__global__ __launch_bounds__(128) void k2(
    const float* __restrict__ W2, const float* __restrict__ W3,
    const float* __restrict__ Wf, float* __restrict__ out)
{
    extern __shared__ __align__(16) unsigned char smraw2[];
    float* w2t = (float*)smraw2;               // [(m*16+h)*132 + k]  16896 f
    float* w3t = w2t + 8 * 16 * 132;           // [h*132 + k]         2112 f
    u64*   h2s = (u64*)(w3t + 16 * 132);       // [slot][m*16+h] pad 132

    const int tid  = threadIdx.x;
    const int h    = tid & 15;
    const int slot = tid >> 4;                 // 0..7
    const int pg0  = blockIdx.x * 8;

    // stage W2 transposed: W2 is [m][k=128][h=16]
    #pragma unroll
    for (int it = 0; it < 32; ++it) {
        int i4 = tid + 128 * it;               // 4096 float4
        int i = i4 * 4;
        float4 v = ((const float4*)W2)[i4];
        int m = i >> 11, k = (i >> 4) & 127, hh = i & 15;
        w2t[(m * 16 + hh + 0) * 132 + k] = v.x;
        w2t[(m * 16 + hh + 1) * 132 + k] = v.y;
        w2t[(m * 16 + hh + 2) * 132 + k] = v.z;
        w2t[(m * 16 + hh + 3) * 132 + k] = v.w;
    }
    // stage W3 transposed: [k=128][h=16]
    #pragma unroll
    for (int it = 0; it < 4; ++it) {
        int i4 = tid + 128 * it;               // 512 float4
        int i = i4 * 4;
        float4 v = ((const float4*)W3)[i4];
        int k = i >> 4, hh = i & 15;
        w3t[(hh + 0) * 132 + k] = v.x;
        w3t[(hh + 1) * 132 + k] = v.y;
        w3t[(hh + 2) * 132 + k] = v.z;
        w3t[(hh + 3) * 132 + k] = v.w;
    }
    __syncthreads();

    const u64* hrow = g_h1 + (size_t)(pg0 + slot) * 1024;

    #pragma unroll 1
    for (int m = 0; m < 8; ++m) {
        const float* w = &w2t[(m * 16 + h) * 132];
        const ulonglong2* av = (const ulonglong2*)(hrow + m * 128);
        u64 acc = 0ull;
        #pragma unroll
        for (int k4 = 0; k4 < 32; ++k4) {
            float4 wv = ((const float4*)w)[k4];
            ulonglong2 aA = av[k4 * 2], aB = av[k4 * 2 + 1];
            acc = ffma2(aA.x, pack2(wv.x, wv.x), acc);
            acc = ffma2(aA.y, pack2(wv.y, wv.y), acc);
            acc = ffma2(aB.x, pack2(wv.z, wv.z), acc);
            acc = ffma2(aB.y, pack2(wv.w, wv.w), acc);
        }
        h2s[slot * 132 + m * 16 + h] = sig2(acc);
    }
    __syncthreads();

    // root + final
    {
        const float* w = &w3t[h * 132];
        const ulonglong2* av = (const ulonglong2*)&h2s[slot * 132];
        u64 acc = 0ull;
        #pragma unroll
        for (int k4 = 0; k4 < 32; ++k4) {
            float4 wv = ((const float4*)w)[k4];
            ulonglong2 aA = av[k4 * 2], aB = av[k4 * 2 + 1];
            acc = ffma2(aA.x, pack2(wv.x, wv.x), acc);
            acc = ffma2(aA.y, pack2(wv.y, wv.y), acc);
            acc = ffma2(aB.x, pack2(wv.z, wv.z), acc);
            acc = ffma2(aB.y, pack2(wv.w, wv.w), acc);
        }
        u64 hrv = sig2(acc);
        float ra, rb; unpack2(hrv, ra, rb);
        float wf = Wf[h];
        ra *= wf; rb *= wf;
        #pragma unroll
        for (int off = 8; off; off >>= 1) {
            ra += __shfl_xor_sync(0xffffffffu, ra, off);
            rb += __shfl_xor_sync(0xffffffffu, rb, off);
        }
        if (h == 0) {
            int pg = pg0 + slot;
            int rowA = (pg >> 5) * 64 + (pg & 31);
            out[rowA]      = ra;
            out[rowA + 32] = rb;
        }
    }
}

static const int K1_SMEM = (32 * 66 + 8 * 16 * 10 + 128 + 32 * 130 + 16 * 130) * 8;
static const int K2_SMEM = (8 * 16 * 132 + 16 * 132) * 4 + 8 * 132 * 8;

extern "C" void kernel_launch(void* const* d_in, const int* in_sizes, int n_in,
                              void* d_out, int out_size)
{
    const float* x  = (const float*)d_in[0];
    const float* Wg = (const float*)d_in[1];
    const float* bg = (const float*)d_in[2];
    const float* W0 = (const float*)d_in[3];
    const float* W1 = (const float*)d_in[4];
    const float* W2 = (const float*)d_in[5];
    const float* W3 = (const float*)d_in[6];
    const float* Wf = (const float*)d_in[7];
    float* out = (float*)d_out;

    cudaFuncSetAttribute(k1, cudaFuncAttributeMaxDynamicSharedMemorySize, K1_SMEM);
    cudaFuncSetAttribute(k2, cudaFuncAttributeMaxDynamicSharedMemorySize, K2_SMEM);

    dim3 g1(B_TOT / 64, 64);
    k1<<<g1, 256, K1_SMEM>>>(x, Wg, bg, W0, W1);
    k2<<<256, 128, K2_SMEM>>>(W2, W3, Wf, out);
}

// round 3
// speedup vs baseline: 1.6002x; 1.6002x over previous
#include <cuda_runtime.h>

// RestrictedNN GB300. B=4096, NINP=4096, L0=512(G=8,H=16), L1=64, L2=8.
// k1: x -> (gene folded) -> h0 -> h1, warp = 64-row tile, lane = row-pair,
//     SIMD = h-pair via fma.rn.f32x2, weights broadcast from smem, h0 in regs.
// k2: scalar f32, h1 -> h2 -> root -> final.
// All sigmoid inputs pre-scaled by -log2(e): sig(z) = rcp(1 + ex2(z')).

#define SCALE (-1.44269504f)

typedef unsigned long long u64;

__device__ float g_h1[(size_t)4096 * 1024];   // [row][g*16+h], 16 MB

__device__ __forceinline__ u64 pack2(float lo, float hi) {
    u64 r; asm("mov.b64 %0, {%1, %2};" : "=l"(r) : "f"(lo), "f"(hi)); return r;
}
__device__ __forceinline__ void unpack2(u64 v, float& lo, float& hi) {
    asm("mov.b64 {%0, %1}, %2;" : "=f"(lo), "=f"(hi) : "l"(v));
}
__device__ __forceinline__ u64 ffma2(u64 a, u64 b, u64 c) {
    u64 d; asm("fma.rn.f32x2 %0, %1, %2, %3;" : "=l"(d) : "l"(a), "l"(b), "l"(c));
    return d;
}
// sigmoid on pre-scaled (z * -log2e) packed pair
__device__ __forceinline__ u64 sig2s(u64 z) {
    float a, b; unpack2(z, a, b);
    float ea, eb, ra, rb;
    asm("ex2.approx.f32 %0, %1;" : "=f"(ea) : "f"(a));
    asm("ex2.approx.f32 %0, %1;" : "=f"(eb) : "f"(b));
    asm("rcp.approx.f32 %0, %1;" : "=f"(ra) : "f"(1.0f + ea));
    asm("rcp.approx.f32 %0, %1;" : "=f"(rb) : "f"(1.0f + eb));
    return pack2(ra, rb);
}
__device__ __forceinline__ float sigs(float z) {   // z pre-scaled
    float e, r;
    asm("ex2.approx.f32 %0, %1;" : "=f"(e) : "f"(z));
    asm("rcp.approx.f32 %0, %1;" : "=f"(r) : "f"(1.0f + e));
    return r;
}

// ---------------------------------------------------------------------------
// K1: grid (8 tile-groups, 64 g), 256 threads = 8 warps; warp -> one 64-row
// tile. Lane p handles rows (tile*64+p, tile*64+p+32).
// ---------------------------------------------------------------------------
__global__ __launch_bounds__(256) void k1(
    const float* __restrict__ x, const float* __restrict__ Wg,
    const float* __restrict__ bgp, const float* __restrict__ W0,
    const float* __restrict__ W1)
{
    __shared__ __align__(16) float w0ps[1024];    // [l][j][h] * Wg * SCALE
    __shared__ __align__(16) float bias0s[128];   // [l][h] * SCALE
    __shared__ __align__(16) float w1s[2048];     // [k][h] * SCALE

    const int g   = blockIdx.y;
    const int tid = threadIdx.x;

    // ---- stage (broadcast-friendly natural layouts, pre-scaled) ----
    {
        float4 v = ((const float4*)(W0 + (size_t)g * 1024))[tid];
        float wg = Wg[g * 64 + (tid >> 2)] * SCALE;
        float4 o; o.x = v.x * wg; o.y = v.y * wg; o.z = v.z * wg; o.w = v.w * wg;
        ((float4*)w0ps)[tid] = o;
    }
    #pragma unroll
    for (int it = 0; it < 2; ++it) {
        int i4 = tid + 256 * it;
        float4 v = ((const float4*)(W1 + (size_t)g * 2048))[i4];
        float4 o; o.x = v.x * SCALE; o.y = v.y * SCALE; o.z = v.z * SCALE; o.w = v.w * SCALE;
        ((float4*)w1s)[i4] = o;
    }
    if (tid < 128) {
        int l = tid >> 4, h = tid & 15;
        const float* bgl = bgp + g * 64 + l * 8;
        const float* w0l = W0 + (size_t)g * 1024 + l * 128 + h;
        float a = 0.f;
        #pragma unroll
        for (int j = 0; j < 8; ++j) a += bgl[j] * w0l[j * 16];
        bias0s[tid] = a * SCALE;
    }
    __syncthreads();

    const int warp = tid >> 5, lane = tid & 31;
    const int tile = blockIdx.x * 8 + warp;
    const int rA = tile * 64 + lane;
    const int rB = rA + 32;
    const float* xA = x + (size_t)rA * 4096 + g * 64;
    const float* xB = x + (size_t)rB * 4096 + g * 64;

    u64 acc1[2][8];
    #pragma unroll
    for (int r = 0; r < 2; ++r)
        #pragma unroll
        for (int hp = 0; hp < 8; ++hp) acc1[r][hp] = 0ull;

    // prefetch leaf 0 x
    float4 pa0 = __ldg((const float4*)xA),     pa1 = __ldg((const float4*)xA + 1);
    float4 pb0 = __ldg((const float4*)xB),     pb1 = __ldg((const float4*)xB + 1);

    #pragma unroll 1
    for (int l = 0; l < 8; ++l) {
        float xa[8], xb[8];
        xa[0]=pa0.x; xa[1]=pa0.y; xa[2]=pa0.z; xa[3]=pa0.w;
        xa[4]=pa1.x; xa[5]=pa1.y; xa[6]=pa1.z; xa[7]=pa1.w;
        xb[0]=pb0.x; xb[1]=pb0.y; xb[2]=pb0.z; xb[3]=pb0.w;
        xb[4]=pb1.x; xb[5]=pb1.y; xb[6]=pb1.z; xb[7]=pb1.w;
        {   // prefetch next leaf (wraps harmlessly on last iter)
            int ln = (l + 1) & 7;
            pa0 = __ldg((const float4*)(xA + ln * 8));
            pa1 = __ldg((const float4*)(xA + ln * 8) + 1);
            pb0 = __ldg((const float4*)(xB + ln * 8));
            pb1 = __ldg((const float4*)(xB + ln * 8) + 1);
        }

        // h0 accumulators: [row][h-pair], init from bias (natural f32-pair LDS)
        u64 acc0[2][8];
        #pragma unroll
        for (int hp = 0; hp < 8; ++hp) {
            u64 b = ((const u64*)bias0s)[l * 8 + hp];
            acc0[0][hp] = b; acc0[1][hp] = b;
        }
        #pragma unroll
        for (int j = 0; j < 8; ++j) {
            u64 dA = pack2(xa[j], xa[j]);
            u64 dB = pack2(xb[j], xb[j]);
            const ulonglong2* wrow = (const ulonglong2*)(w0ps + l * 128 + j * 16);
            #pragma unroll
            for (int hq = 0; hq < 4; ++hq) {
                ulonglong2 w = wrow[hq];                 // broadcast LDS.128
                acc0[0][hq*2]   = ffma2(dA, w.x, acc0[0][hq*2]);
                acc0[0][hq*2+1] = ffma2(dA, w.y, acc0[0][hq*2+1]);
                acc0[1][hq*2]   = ffma2(dB, w.x, acc0[1][hq*2]);
                acc0[1][hq*2+1] = ffma2(dB, w.y, acc0[1][hq*2+1]);
            }
        }

        // sigmoid(h0) and immediately accumulate into h1
        #pragma unroll
        for (int hp = 0; hp < 8; ++hp) {
            const int k0 = l * 16 + hp * 2;
            const ulonglong2* wr0 = (const ulonglong2*)(w1s + k0 * 16);
            const ulonglong2* wr1 = (const ulonglong2*)(w1s + (k0 + 1) * 16);
            ulonglong2 wa0 = wr0[0], wa1 = wr0[1], wa2 = wr0[2], wa3 = wr0[3];
            ulonglong2 wb0 = wr1[0], wb1 = wr1[1], wb2 = wr1[2], wb3 = wr1[3];
            #pragma unroll
            for (int r = 0; r < 2; ++r) {
                u64 s = sig2s(acc0[r][hp]);
                float s0, s1; unpack2(s, s0, s1);
                u64 d0 = pack2(s0, s0), d1 = pack2(s1, s1);
                acc1[r][0] = ffma2(d0, wa0.x, acc1[r][0]);
                acc1[r][1] = ffma2(d0, wa0.y, acc1[r][1]);
                acc1[r][2] = ffma2(d0, wa1.x, acc1[r][2]);
                acc1[r][3] = ffma2(d0, wa1.y, acc1[r][3]);
                acc1[r][4] = ffma2(d0, wa2.x, acc1[r][4]);
                acc1[r][5] = ffma2(d0, wa2.y, acc1[r][5]);
                acc1[r][6] = ffma2(d0, wa3.x, acc1[r][6]);
                acc1[r][7] = ffma2(d0, wa3.y, acc1[r][7]);
                acc1[r][0] = ffma2(d1, wb0.x, acc1[r][0]);
                acc1[r][1] = ffma2(d1, wb0.y, acc1[r][1]);
                acc1[r][2] = ffma2(d1, wb1.x, acc1[r][2]);
                acc1[r][3] = ffma2(d1, wb1.y, acc1[r][3]);
                acc1[r][4] = ffma2(d1, wb2.x, acc1[r][4]);
                acc1[r][5] = ffma2(d1, wb2.y, acc1[r][5]);
                acc1[r][6] = ffma2(d1, wb3.x, acc1[r][6]);
                acc1[r][7] = ffma2(d1, wb3.y, acc1[r][7]);
            }
        }
    }

    // finalize h1: sigmoid, unpack, store 64B per row
    #pragma unroll
    for (int r = 0; r < 2; ++r) {
        float o[16];
        #pragma unroll
        for (int hp = 0; hp < 8; ++hp) {
            u64 s = sig2s(acc1[r][hp]);
            unpack2(s, o[hp * 2], o[hp * 2 + 1]);
        }
        float* dst = g_h1 + (size_t)(r ? rB : rA) * 1024 + g * 16;
        ((float4*)dst)[0] = make_float4(o[0],  o[1],  o[2],  o[3]);
        ((float4*)dst)[1] = make_float4(o[4],  o[5],  o[6],  o[7]);
        ((float4*)dst)[2] = make_float4(o[8],  o[9],  o[10], o[11]);
        ((float4*)dst)[3] = make_float4(o[12], o[13], o[14], o[15]);
    }
}

// ---------------------------------------------------------------------------
// K2: grid 256, 256 threads = 16 rows x 16 h, scalar fp32.
// smem 84.5 KB -> 2 blocks/SM. h2 (8x 128->16), root (128->16), final dot.
// ---------------------------------------------------------------------------
__global__ __launch_bounds__(256) void k2(
    const float* __restrict__ W2, const float* __restrict__ W3,
    const float* __restrict__ Wf, float* __restrict__ out)
{
    extern __shared__ __align__(16) unsigned char smraw2[];
    float* w2t = (float*)smraw2;               // [(m*16+h)][132]
    float* w3t = w2t + 8 * 16 * 132;           // [h][132]
    float* h2s = w3t + 16 * 132;               // [slot][132]

    const int tid  = threadIdx.x;
    const int h    = tid & 15;
    const int slot = tid >> 4;
    const int row  = blockIdx.x * 16 + slot;

    // stage W2 transposed (pre-scaled): W2 is [m][k=128][h=16]
    #pragma unroll
    for (int it = 0; it < 16; ++it) {
        int i4 = tid + 256 * it;               // 4096 float4
        int i = i4 * 4;
        float4 v = ((const float4*)W2)[i4];
        int m = i >> 11, k = (i >> 4) & 127, hh = i & 15;
        w2t[(m * 16 + hh + 0) * 132 + k] = v.x * SCALE;
        w2t[(m * 16 + hh + 1) * 132 + k] = v.y * SCALE;
        w2t[(m * 16 + hh + 2) * 132 + k] = v.z * SCALE;
        w2t[(m * 16 + hh + 3) * 132 + k] = v.w * SCALE;
    }
    // stage W3 transposed (pre-scaled): [k=128][h=16]
    #pragma unroll
    for (int it = 0; it < 2; ++it) {
        int i4 = tid + 256 * it;               // 512 float4
        int i = i4 * 4;
        float4 v = ((const float4*)W3)[i4];
        int k = i >> 4, hh = i & 15;
        w3t[(hh + 0) * 132 + k] = v.x * SCALE;
        w3t[(hh + 1) * 132 + k] = v.y * SCALE;
        w3t[(hh + 2) * 132 + k] = v.z * SCALE;
        w3t[(hh + 3) * 132 + k] = v.w * SCALE;
    }
    __syncthreads();

    const float4* act = (const float4*)(g_h1 + (size_t)row * 1024);

    #pragma unroll 1
    for (int m = 0; m < 8; ++m) {
        const float4* w = (const float4*)(w2t + (m * 16 + h) * 132);
        float acc = 0.f;
        #pragma unroll
        for (int k4 = 0; k4 < 32; ++k4) {
            float4 a = __ldg(act + m * 32 + k4);     // broadcast across h lanes
            float4 wv = w[k4];
            acc += a.x * wv.x + a.y * wv.y + a.z * wv.z + a.w * wv.w;
        }
        h2s[slot * 132 + m * 16 + h] = sigs(acc);
    }
    __syncthreads();

    // root + final
    {
        const float4* a = (const float4*)(h2s + slot * 132);
        const float4* w = (const float4*)(w3t + h * 132);
        float acc = 0.f;
        #pragma unroll
        for (int k4 = 0; k4 < 32; ++k4) {
            float4 av = a[k4], wv = w[k4];
            acc += av.x * wv.x + av.y * wv.y + av.z * wv.z + av.w * wv.w;
        }
        float yv = sigs(acc) * __ldg(Wf + h);
        #pragma unroll
        for (int off = 8; off; off >>= 1)
            yv += __shfl_xor_sync(0xffffffffu, yv, off);
        if (h == 0) out[row] = yv;
    }
}

static const int K2_SMEM = (8 * 16 * 132 + 16 * 132 + 16 * 132) * 4;   // 84480 B

extern "C" void kernel_launch(void* const* d_in, const int* in_sizes, int n_in,
                              void* d_out, int out_size)
{
    const float* x  = (const float*)d_in[0];
    const float* Wg = (const float*)d_in[1];
    const float* bg = (const float*)d_in[2];
    const float* W0 = (const float*)d_in[3];
    const float* W1 = (const float*)d_in[4];
    const float* W2 = (const float*)d_in[5];
    const float* W3 = (const float*)d_in[6];
    const float* Wf = (const float*)d_in[7];
    float* out = (float*)d_out;

    cudaFuncSetAttribute(k2, cudaFuncAttributeMaxDynamicSharedMemorySize, K2_SMEM);

    dim3 g1(8, 64);
    k1<<<g1, 256>>>(x, Wg, bg, W0, W1);
    k2<<<256, 256, K2_SMEM>>>(W2, W3, Wf, out);
}

// round 5
// speedup vs baseline: 2.0463x; 1.2788x over previous
#include <cuda_runtime.h>

// RestrictedNN GB300. B=4096, NINP=4096, L0=512(G=8,H=16), L1=64, L2=8.
// k1: x -> (gene folded) -> h0 -> h1. warp = 64-row tile, lane = row-pair,
//     SIMD = h-pairs via fma.rn.f32x2, weights broadcast from smem, h0 in regs.
//     h1 written TRANSPOSED: g_h1T[feature][row] (coalesced STG.32).
// k2: same SIMD style. Block = 32 rows x 8 warps; warp w does h2-module w
//     (weights broadcast from smem in natural [k][h] layout), then root
//     partial over k-chunk, smem tree-reduce, in-lane Wf dot.
// All sigmoid inputs pre-scaled by -log2(e): sig(z) = rcp(1 + ex2(z)).

#define SCALE (-1.44269504f)

typedef unsigned long long u64;

__device__ float g_h1T[(size_t)1024 * 4096];   // [feature][row], 16 MB

__device__ __forceinline__ u64 pack2(float lo, float hi) {
    u64 r; asm("mov.b64 %0, {%1, %2};" : "=l"(r) : "f"(lo), "f"(hi)); return r;
}
__device__ __forceinline__ void unpack2(u64 v, float& lo, float& hi) {
    asm("mov.b64 {%0, %1}, %2;" : "=f"(lo), "=f"(hi) : "l"(v));
}
__device__ __forceinline__ u64 ffma2(u64 a, u64 b, u64 c) {
    u64 d; asm("fma.rn.f32x2 %0, %1, %2, %3;" : "=l"(d) : "l"(a), "l"(b), "l"(c));
    return d;
}
__device__ __forceinline__ u64 add2(u64 a, u64 b) {
    u64 d; asm("add.rn.f32x2 %0, %1, %2;" : "=l"(d) : "l"(a), "l"(b));
    return d;
}
// sigmoid on pre-scaled (z * -log2e) packed pair
__device__ __forceinline__ u64 sig2s(u64 z) {
    float a, b; unpack2(z, a, b);
    float ea, eb, ra, rb;
    asm("ex2.approx.f32 %0, %1;" : "=f"(ea) : "f"(a));
    asm("ex2.approx.f32 %0, %1;" : "=f"(eb) : "f"(b));
    asm("rcp.approx.f32 %0, %1;" : "=f"(ra) : "f"(1.0f + ea));
    asm("rcp.approx.f32 %0, %1;" : "=f"(rb) : "f"(1.0f + eb));
    return pack2(ra, rb);
}

// ---------------------------------------------------------------------------
// K1: grid (8 tile-groups, 64 g), 256 threads = 8 warps; warp -> one 64-row
// tile. Lane p handles rows (tile*64+p, tile*64+p+32).
// ---------------------------------------------------------------------------
__global__ __launch_bounds__(256) void k1(
    const float* __restrict__ x, const float* __restrict__ Wg,
    const float* __restrict__ bgp, const float* __restrict__ W0,
    const float* __restrict__ W1)
{
    __shared__ __align__(16) float w0ps[1024];    // [l][j][h] * Wg * SCALE
    __shared__ __align__(16) float bias0s[128];   // [l][h] * SCALE
    __shared__ __align__(16) float w1s[2048];     // [k][h] * SCALE

    const int g   = blockIdx.y;
    const int tid = threadIdx.x;

    {
        float4 v = ((const float4*)(W0 + (size_t)g * 1024))[tid];
        float wg = Wg[g * 64 + (tid >> 2)] * SCALE;
        float4 o; o.x = v.x * wg; o.y = v.y * wg; o.z = v.z * wg; o.w = v.w * wg;
        ((float4*)w0ps)[tid] = o;
    }
    #pragma unroll
    for (int it = 0; it < 2; ++it) {
        int i4 = tid + 256 * it;
        float4 v = ((const float4*)(W1 + (size_t)g * 2048))[i4];
        float4 o; o.x = v.x * SCALE; o.y = v.y * SCALE; o.z = v.z * SCALE; o.w = v.w * SCALE;
        ((float4*)w1s)[i4] = o;
    }
    if (tid < 128) {
        int l = tid >> 4, h = tid & 15;
        const float* bgl = bgp + g * 64 + l * 8;
        const float* w0l = W0 + (size_t)g * 1024 + l * 128 + h;
        float a = 0.f;
        #pragma unroll
        for (int j = 0; j < 8; ++j) a += bgl[j] * w0l[j * 16];
        bias0s[tid] = a * SCALE;
    }
    __syncthreads();

    const int warp = tid >> 5, lane = tid & 31;
    const int tile = blockIdx.x * 8 + warp;
    const int rA = tile * 64 + lane;
    const int rB = rA + 32;
    const float* xA = x + (size_t)rA * 4096 + g * 64;
    const float* xB = x + (size_t)rB * 4096 + g * 64;

    u64 acc1[2][8];
    #pragma unroll
    for (int r = 0; r < 2; ++r)
        #pragma unroll
        for (int hp = 0; hp < 8; ++hp) acc1[r][hp] = 0ull;

    float4 pa0 = __ldg((const float4*)xA), pa1 = __ldg((const float4*)xA + 1);
    float4 pb0 = __ldg((const float4*)xB), pb1 = __ldg((const float4*)xB + 1);

    #pragma unroll 1
    for (int l = 0; l < 8; ++l) {
        float xa[8], xb[8];
        xa[0]=pa0.x; xa[1]=pa0.y; xa[2]=pa0.z; xa[3]=pa0.w;
        xa[4]=pa1.x; xa[5]=pa1.y; xa[6]=pa1.z; xa[7]=pa1.w;
        xb[0]=pb0.x; xb[1]=pb0.y; xb[2]=pb0.z; xb[3]=pb0.w;
        xb[4]=pb1.x; xb[5]=pb1.y; xb[6]=pb1.z; xb[7]=pb1.w;
        {
            int ln = (l + 1) & 7;
            pa0 = __ldg((const float4*)(xA + ln * 8));
            pa1 = __ldg((const float4*)(xA + ln * 8) + 1);
            pb0 = __ldg((const float4*)(xB + ln * 8));
            pb1 = __ldg((const float4*)(xB + ln * 8) + 1);
        }

        u64 acc0[2][8];
        #pragma unroll
        for (int hp = 0; hp < 8; ++hp) {
            u64 b = ((const u64*)bias0s)[l * 8 + hp];
            acc0[0][hp] = b; acc0[1][hp] = b;
        }
        #pragma unroll
        for (int j = 0; j < 8; ++j) {
            u64 dA = pack2(xa[j], xa[j]);
            u64 dB = pack2(xb[j], xb[j]);
            const ulonglong2* wrow = (const ulonglong2*)(w0ps + l * 128 + j * 16);
            #pragma unroll
            for (int hq = 0; hq < 4; ++hq) {
                ulonglong2 w = wrow[hq];                 // broadcast
                acc0[0][hq*2]   = ffma2(dA, w.x, acc0[0][hq*2]);
                acc0[0][hq*2+1] = ffma2(dA, w.y, acc0[0][hq*2+1]);
                acc0[1][hq*2]   = ffma2(dB, w.x, acc0[1][hq*2]);
                acc0[1][hq*2+1] = ffma2(dB, w.y, acc0[1][hq*2+1]);
            }
        }

        #pragma unroll
        for (int hp = 0; hp < 8; ++hp) {
            const int k0 = l * 16 + hp * 2;
            const ulonglong2* wr0 = (const ulonglong2*)(w1s + k0 * 16);
            const ulonglong2* wr1 = (const ulonglong2*)(w1s + (k0 + 1) * 16);
            ulonglong2 wa0 = wr0[0], wa1 = wr0[1], wa2 = wr0[2], wa3 = wr0[3];
            ulonglong2 wb0 = wr1[0], wb1 = wr1[1], wb2 = wr1[2], wb3 = wr1[3];
            #pragma unroll
            for (int r = 0; r < 2; ++r) {
                u64 s = sig2s(acc0[r][hp]);
                float s0, s1; unpack2(s, s0, s1);
                u64 d0 = pack2(s0, s0), d1 = pack2(s1, s1);
                acc1[r][0] = ffma2(d0, wa0.x, acc1[r][0]);
                acc1[r][1] = ffma2(d0, wa0.y, acc1[r][1]);
                acc1[r][2] = ffma2(d0, wa1.x, acc1[r][2]);
                acc1[r][3] = ffma2(d0, wa1.y, acc1[r][3]);
                acc1[r][4] = ffma2(d0, wa2.x, acc1[r][4]);
                acc1[r][5] = ffma2(d0, wa2.y, acc1[r][5]);
                acc1[r][6] = ffma2(d0, wa3.x, acc1[r][6]);
                acc1[r][7] = ffma2(d0, wa3.y, acc1[r][7]);
                acc1[r][0] = ffma2(d1, wb0.x, acc1[r][0]);
                acc1[r][1] = ffma2(d1, wb0.y, acc1[r][1]);
                acc1[r][2] = ffma2(d1, wb1.x, acc1[r][2]);
                acc1[r][3] = ffma2(d1, wb1.y, acc1[r][3]);
                acc1[r][4] = ffma2(d1, wb2.x, acc1[r][4]);
                acc1[r][5] = ffma2(d1, wb2.y, acc1[r][5]);
                acc1[r][6] = ffma2(d1, wb3.x, acc1[r][6]);
                acc1[r][7] = ffma2(d1, wb3.y, acc1[r][7]);
            }
        }
    }

    // finalize h1: sigmoid, store TRANSPOSED (coalesced across lanes)
    #pragma unroll
    for (int r = 0; r < 2; ++r) {
        const int row = r ? rB : rA;
        #pragma unroll
        for (int hp = 0; hp < 8; ++hp) {
            u64 s = sig2s(acc1[r][hp]);
            float s0, s1; unpack2(s, s0, s1);
            g_h1T[(size_t)(g * 16 + hp * 2)     * 4096 + row] = s0;
            g_h1T[(size_t)(g * 16 + hp * 2 + 1) * 4096 + row] = s1;
        }
    }
}

// ---------------------------------------------------------------------------
// K2: grid 128, 256 threads = 8 warps. lane = row (row0+lane), f32x2 h-pairs.
// warp w: h2-module m=w, then root partial over k-chunk [w*16,(w+1)*16).
// ---------------------------------------------------------------------------
#define H2S_FLOATS (32 * 129 + 4)   // +4 keeps the following u64 region 8B-aligned

__global__ __launch_bounds__(256) void k2(
    const float* __restrict__ W2, const float* __restrict__ W3,
    const float* __restrict__ Wf, float* __restrict__ out)
{
    extern __shared__ __align__(16) unsigned char smraw2[];
    float* w2s   = (float*)smraw2;             // [m][k][h] * SCALE, 16384 f
    float* w3s   = w2s + 16384;                // [k][h]  * SCALE, 2048 f
    float* h2s   = w3s + 2048;                 // [row_lane][129]
    u64*   part  = (u64*)(h2s + H2S_FLOATS);   // [hp][w][lane] = [8][8][32], 8B-aligned
    float* fpart = (float*)(part + 2048);      // [w][lane]

    const int tid  = threadIdx.x;
    const int warp = tid >> 5;
    const int lane = tid & 31;
    const int row0 = blockIdx.x * 32;

    // stage W2, W3 (pre-scaled), natural [k][h] layout
    #pragma unroll
    for (int it = 0; it < 16; ++it) {
        int i4 = tid + 256 * it;               // 4096 float4
        float4 v = ((const float4*)W2)[i4];
        float4 o; o.x = v.x * SCALE; o.y = v.y * SCALE; o.z = v.z * SCALE; o.w = v.w * SCALE;
        ((float4*)w2s)[i4] = o;
    }
    #pragma unroll
    for (int it = 0; it < 2; ++it) {
        int i4 = tid + 256 * it;               // 512 float4
        float4 v = ((const float4*)W3)[i4];
        float4 o; o.x = v.x * SCALE; o.y = v.y * SCALE; o.z = v.z * SCALE; o.w = v.w * SCALE;
        ((float4*)w3s)[i4] = o;
    }
    __syncthreads();

    // ---- h2 module m = warp: acc over 128 features ----
    {
        u64 acc[8];
        #pragma unroll
        for (int hp = 0; hp < 8; ++hp) acc[hp] = 0ull;

        const float* actc = g_h1T + (size_t)(warp * 128) * 4096 + row0 + lane;
        const float* wbase = w2s + warp * 128 * 16;

        #pragma unroll 16
        for (int j = 0; j < 128; ++j) {
            float a = __ldg(actc + (size_t)j * 4096);    // coalesced across lanes
            u64 d = pack2(a, a);
            const ulonglong2* wr = (const ulonglong2*)(wbase + j * 16);
            ulonglong2 w0 = wr[0], w1 = wr[1], w2v = wr[2], w3v = wr[3];
            acc[0] = ffma2(d, w0.x,  acc[0]);
            acc[1] = ffma2(d, w0.y,  acc[1]);
            acc[2] = ffma2(d, w1.x,  acc[2]);
            acc[3] = ffma2(d, w1.y,  acc[3]);
            acc[4] = ffma2(d, w2v.x, acc[4]);
            acc[5] = ffma2(d, w2v.y, acc[5]);
            acc[6] = ffma2(d, w3v.x, acc[6]);
            acc[7] = ffma2(d, w3v.y, acc[7]);
        }
        #pragma unroll
        for (int hp = 0; hp < 8; ++hp) {
            u64 s = sig2s(acc[hp]);
            float s0, s1; unpack2(s, s0, s1);
            h2s[lane * 129 + warp * 16 + hp * 2]     = s0;
            h2s[lane * 129 + warp * 16 + hp * 2 + 1] = s1;
        }
    }
    __syncthreads();

    // ---- root partial: warp w covers k in [w*16, (w+1)*16) ----
    {
        u64 racc[8];
        #pragma unroll
        for (int hp = 0; hp < 8; ++hp) racc[hp] = 0ull;
        #pragma unroll
        for (int jj = 0; jj < 16; ++jj) {
            int jg = warp * 16 + jj;
            float a = h2s[lane * 129 + jg];              // conflict-free (129)
            u64 d = pack2(a, a);
            const ulonglong2* wr = (const ulonglong2*)(w3s + jg * 16);
            ulonglong2 w0 = wr[0], w1 = wr[1], w2v = wr[2], w3v = wr[3];
            racc[0] = ffma2(d, w0.x,  racc[0]);
            racc[1] = ffma2(d, w0.y,  racc[1]);
            racc[2] = ffma2(d, w1.x,  racc[2]);
            racc[3] = ffma2(d, w1.y,  racc[3]);
            racc[4] = ffma2(d, w2v.x, racc[4]);
            racc[5] = ffma2(d, w2v.y, racc[5]);
            racc[6] = ffma2(d, w3v.x, racc[6]);
            racc[7] = ffma2(d, w3v.y, racc[7]);
        }
        #pragma unroll
        for (int hp = 0; hp < 8; ++hp)
            part[hp * 256 + warp * 32 + lane] = racc[hp];
    }
    __syncthreads();

    // ---- reduce: warp w handles h-pair hp=w -> contrib = sig*Wf ----
    {
        u64 s = part[warp * 256 + lane];
        #pragma unroll
        for (int ww = 1; ww < 8; ++ww)
            s = add2(s, part[warp * 256 + ww * 32 + lane]);
        u64 sg = sig2s(s);
        float s0, s1; unpack2(sg, s0, s1);
        float c = s0 * __ldg(Wf + warp * 2) + s1 * __ldg(Wf + warp * 2 + 1);
        fpart[warp * 32 + lane] = c;
    }
    __syncthreads();

    if (warp == 0) {
        float a = fpart[lane];
        #pragma unroll
        for (int ww = 1; ww < 8; ++ww) a += fpart[ww * 32 + lane];
        out[row0 + lane] = a;
    }
}

static const int K2_SMEM = (16384 + 2048 + H2S_FLOATS) * 4 + 2048 * 8 + 256 * 4;

extern "C" void kernel_launch(void* const* d_in, const int* in_sizes, int n_in,
                              void* d_out, int out_size)
{
    const float* x  = (const float*)d_in[0];
    const float* Wg = (const float*)d_in[1];
    const float* bg = (const float*)d_in[2];
    const float* W0 = (const float*)d_in[3];
    const float* W1 = (const float*)d_in[4];
    const float* W2 = (const float*)d_in[5];
    const float* W3 = (const float*)d_in[6];
    const float* Wf = (const float*)d_in[7];
    float* out = (float*)d_out;

    cudaFuncSetAttribute(k2, cudaFuncAttributeMaxDynamicSharedMemorySize, K2_SMEM);

    dim3 g1(8, 64);
    k1<<<g1, 256>>>(x, Wg, bg, W0, W1);
    k2<<<128, 256, K2_SMEM>>>(W2, W3, Wf, out);
}